// round 7
// baseline (speedup 1.0000x reference)
#include <cuda_runtime.h>
#include <math.h>
#include <stdint.h>

#define Bb   8
#define Cc   256
#define Hh   64
#define Ww   64
#define Gg   16
#define Dd   16
#define Pp   3
#define CRr  64
#define NT   49
#define NTP  52        // taps padded: 4 warps * 13
#define TPW  13
#define KKG  784
#define HW   4096
#define EPSf 1e-5f

// ---------------- packed f32x2 helpers ---------------------------------------
typedef unsigned long long ull;
#define FMA2(acc, a, b) asm("fma.rn.f32x2 %0, %1, %2, %0;" : "+l"(acc) : "l"(a), "l"(b))
#define ADD2(acc, a)    asm("add.rn.f32x2 %0, %0, %1;"     : "+l"(acc) : "l"(a))
#define PACK2(d, lo, hi) asm("mov.b64 %0, {%1, %2};" : "=l"(d) : "f"(lo), "f"(hi))
#define UNPACK2(lo, hi, s) asm("mov.b64 {%0, %1}, %2;" : "=f"(lo), "=f"(hi) : "l"(s))
#define LDSV2(lo, hi, addr) \
    asm volatile("ld.shared.v2.u64 {%0, %1}, [%2];" : "=l"(lo), "=l"(hi) : "r"(addr))
#define STSV2(addr, lo, hi) \
    asm volatile("st.shared.v2.u64 [%0], {%1, %2};" :: "r"(addr), "l"(lo), "l"(hi))
#define LDS32(dst, addr) \
    asm volatile("ld.shared.f32 %0, [%1];" : "=f"(dst) : "r"(addr))

static __device__ __forceinline__ uint32_t saddr(const void* p) {
    return (uint32_t)__cvta_generic_to_shared(p);
}

// ---------------- device-global scratch --------------------------------------
__device__ float g_wrT[Cc * CRr];                        // reduce weights [k][m]
__device__ float g_br[CRr];
__device__ __align__(16) float g_ws4[Gg * 32 * NTP * 4]; // [g][k2][tap]{wk,wk,wk1,wk1}
__device__ float g_bsp[KKG];
__device__ float g_r[(size_t)Bb * CRr * HW];             // reduce output [b][c][hw]

// ---------------- weight preparation (warp per row) ---------------------------
__global__ __launch_bounds__(256) void prep_weights(
        const float* __restrict__ v_reduce, const float* __restrict__ g_reduce,
        const float* __restrict__ b_reduce, const float* __restrict__ bn_gamma,
        const float* __restrict__ bn_beta,  const float* __restrict__ bn_mean,
        const float* __restrict__ bn_var,   const float* __restrict__ v_span,
        const float* __restrict__ g_span,   const float* __restrict__ b_span) {
    int row  = blockIdx.x * 8 + (threadIdx.x >> 5);
    int lane = threadIdx.x & 31;
    if (row < CRr) {
        float v[8];
        float s = 0.f;
#pragma unroll
        for (int i = 0; i < 8; i++) {
            v[i] = v_reduce[row * Cc + lane + i * 32];
            s += v[i] * v[i];
        }
#pragma unroll
        for (int off = 16; off > 0; off >>= 1)
            s += __shfl_xor_sync(0xffffffffu, s, off);
        float scale = bn_gamma[row] * rsqrtf(bn_var[row] + EPSf);
        float wmul  = g_reduce[row] / sqrtf(s) * scale;
#pragma unroll
        for (int i = 0; i < 8; i++)
            g_wrT[(lane + i * 32) * CRr + row] = v[i] * wmul;
        if (lane == 0)
            g_br[row] = (b_reduce[row] - bn_mean[row]) * scale + bn_beta[row];
    } else if (row < CRr + KKG) {
        int o = row - CRr;            // o = tap*16 + g
        int tap = o >> 4;
        int gq  = o & 15;
        float v0 = v_span[o * CRr + lane];
        float v1 = v_span[o * CRr + 32 + lane];
        float s = v0 * v0 + v1 * v1;
#pragma unroll
        for (int off = 16; off > 0; off >>= 1)
            s += __shfl_xor_sync(0xffffffffu, s, off);
        float wmul = g_span[o] / sqrtf(s);
        float w0 = v0 * wmul, w1 = v1 * wmul;
        int c0 = lane, c1 = lane + 32;
        int i0 = ((gq * 32 + (c0 >> 1)) * NTP + tap) * 4 + (c0 & 1) * 2;
        int i1 = ((gq * 32 + (c1 >> 1)) * NTP + tap) * 4 + (c1 & 1) * 2;
        g_ws4[i0] = w0; g_ws4[i0 + 1] = w0;
        g_ws4[i1] = w1; g_ws4[i1 + 1] = w1;
        if (lane == 0) g_bsp[o] = b_span[o];
    } else if (row < CRr + KKG + Gg * 3) {
        int p = row - (CRr + KKG);    // zero-pad taps 49..51
        int gq = p / 3;
        int tap = NT + p % 3;
        int c0 = lane, c1 = lane + 32;
        int i0 = ((gq * 32 + (c0 >> 1)) * NTP + tap) * 4 + (c0 & 1) * 2;
        int i1 = ((gq * 32 + (c1 >> 1)) * NTP + tap) * 4 + (c1 & 1) * 2;
        g_ws4[i0] = 0.f; g_ws4[i0 + 1] = 0.f;
        g_ws4[i1] = 0.f; g_ws4[i1 + 1] = 0.f;
    }
}

// ---------------- reduce GEMM: m=64 x n=128 px, 256 CTAs ----------------------
__global__ __launch_bounds__(256) void reduce_gemm(const float* __restrict__ x) {
    __shared__ float As[16][64];
    __shared__ float Bs[16][128];
    int b  = blockIdx.z;
    int n0 = blockIdx.x * 128;
    int tid = threadIdx.x;
    int ty = tid >> 5;           // m-octet 0..7
    int tx = tid & 31;           // 4 px each
    const float* xb = x + (size_t)b * Cc * HW;

    ull acc2[4][4];              // m-pairs x px
#pragma unroll
    for (int i = 0; i < 4; i++)
#pragma unroll
        for (int j = 0; j < 4; j++) acc2[i][j] = 0ull;

    for (int k0 = 0; k0 < Cc; k0 += 16) {
        {
            int kr = tid >> 4, m4 = (tid & 15) * 4;
            *(float4*)&As[kr][m4] = *(const float4*)&g_wrT[(k0 + kr) * CRr + m4];
        }
#pragma unroll
        for (int q = 0; q < 2; q++) {
            int f = q * 256 + tid;
            int kr = f >> 5, c4 = (f & 31) * 4;
            *(float4*)&Bs[kr][c4] = *(const float4*)(xb + (size_t)(k0 + kr) * HW + n0 + c4);
        }
        __syncthreads();
#pragma unroll
        for (int k = 0; k < 16; k++) {
            ull a0, a1, a2, a3;
            LDSV2(a0, a1, saddr(&As[k][ty * 8]));
            LDSV2(a2, a3, saddr(&As[k][ty * 8 + 4]));
            float4 bv = *(float4*)&Bs[k][tx * 4];
            float bs[4] = {bv.x, bv.y, bv.z, bv.w};
            ull bd[4];
#pragma unroll
            for (int j = 0; j < 4; j++) PACK2(bd[j], bs[j], bs[j]);
            ull aa[4] = {a0, a1, a2, a3};
#pragma unroll
            for (int i = 0; i < 4; i++)
#pragma unroll
                for (int j = 0; j < 4; j++)
                    FMA2(acc2[i][j], aa[i], bd[j]);
        }
        __syncthreads();
    }

    float bia[8];
#pragma unroll
    for (int i = 0; i < 8; i++) bia[i] = g_br[ty * 8 + i];
    float* rb = g_r + (size_t)b * CRr * HW;
#pragma unroll
    for (int i = 0; i < 4; i++) {
        float f[2][4];
#pragma unroll
        for (int j = 0; j < 4; j++) {
            float lo, hi;
            UNPACK2(lo, hi, acc2[i][j]);
            f[0][j] = fmaxf(lo + bia[2 * i], 0.f);
            f[1][j] = fmaxf(hi + bia[2 * i + 1], 0.f);
        }
#pragma unroll
        for (int h = 0; h < 2; h++) {
            int m = ty * 8 + 2 * i + h;
            *(float4*)(rb + (size_t)m * HW + n0 + tx * 4) =
                make_float4(f[h][0], f[h][1], f[h][2], f[h][3]);
        }
    }
}

// ---------------- fused span + involution (8x16 tile, 2 CTAs/SM) --------------
#define TSX  16
#define TSY  8
#define NPX  128
#define XDX  22
#define XDY  14
#define XSTR 18         // (8*18) % 32 = 16 -> conflict-free dual-pg LDS.32
#define KST  132
#define OFF_RS   0                      // 64k x 128px fp32   = 32768 B
#define OFF_WS   32768                  // 32 x 52 x 16B      = 26624 B
#define OFF_XS   59392                  // 308 x 18 x 4       = 22176 B
#define OFF_KER  81568                  // 49 x 132 x 4       = 25872 B
#define OFF_BS   107440                 // 52 x 4
#define SMEM_REQ 107648

extern __shared__ char smraw[];

__global__ __launch_bounds__(256, 2) void fused_kernel(
        const float* __restrict__ x, float* __restrict__ out) {
    int tid  = threadIdx.x;
    int wid  = tid >> 5;
    int lane = tid & 31;
    int bz = blockIdx.z;
    int b = bz >> 4, g = bz & 15;
    int h0 = blockIdx.y * TSY, w0 = blockIdx.x * TSX;
    uint32_t sb = saddr(smraw);

    // ---- cooperative loads: rs + ws + bias --------------------------------------
    {
        const float* rb = g_r + (size_t)b * CRr * HW;
        float* rs = (float*)(smraw + OFF_RS);
#pragma unroll
        for (int it = 0; it < 8; it++) {
            int i = tid + it * 256;          // 2048 float4
            int c = i >> 5, rem = i & 31;
            int y = rem >> 2, x4 = (rem & 3) << 2;
            float4 v = *(const float4*)(rb + (size_t)c * HW + (h0 + y) * Ww + w0 + x4);
            *(float4*)(rs + c * NPX + y * 16 + x4) = v;
        }
    }
    {
        const uint4* src = (const uint4*)g_ws4 + (size_t)g * (32 * NTP);
        uint4* dst = (uint4*)(smraw + OFF_WS);
#pragma unroll
        for (int it = 0; it < 7; it++) {
            int i = tid + it * 256;
            if (i < 32 * NTP) dst[i] = src[i];
        }
    }
    if (tid < NTP)
        ((float*)(smraw + OFF_BS))[tid] = (tid < NT) ? g_bsp[tid * Gg + g] : 0.f;
    __syncthreads();

    // ---- phase 1: warps 0-3 (13 taps, rs double-buffered) | warps 4-7 halo ------
    if (wid < 4) {
        ull acc2[TPW][2];
#pragma unroll
        for (int i = 0; i < TPW; i++) { acc2[i][0] = 0ull; acc2[i][1] = 0ull; }

        uint32_t rs_a = sb + OFF_RS + lane * 16;
        uint32_t ws_a = sb + OFF_WS + wid * TPW * 16;
        ull b0, b1, c0, c1;
        LDSV2(b0, b1, rs_a);
        LDSV2(c0, c1, rs_a + 512);
#pragma unroll 2
        for (int k2 = 0; k2 < 32; k2++) {
            ull nb0, nb1, nc0, nc1;   // prefetch next (k2=31 overreads ws: harmless)
            uint32_t rn = rs_a + (k2 + 1) * 1024;
            LDSV2(nb0, nb1, rn);
            LDSV2(nc0, nc1, rn + 512);
            uint32_t wa = ws_a + k2 * (NTP * 16);
#pragma unroll
            for (int i = 0; i < TPW; i++) {
                ull a0, a1;
                LDSV2(a0, a1, wa + i * 16);
                FMA2(acc2[i][0], a0, b0);
                FMA2(acc2[i][1], a0, b1);
                FMA2(acc2[i][0], a1, c0);
                FMA2(acc2[i][1], a1, c1);
            }
            b0 = nb0; b1 = nb1; c0 = nc0; c1 = nc1;
        }
        float* bs = (float*)(smraw + OFF_BS);
#pragma unroll
        for (int i = 0; i < TPW; i++) {
            int tap = wid * TPW + i;
            if (tap < NT) {
                ull bp;
                float bv = bs[tap];
                PACK2(bp, bv, bv);
                ADD2(acc2[i][0], bp);
                ADD2(acc2[i][1], bp);
                STSV2(sb + OFF_KER + tap * (KST * 4) + lane * 16,
                      acc2[i][0], acc2[i][1]);
            }
        }
    } else {
        float* xs = (float*)(smraw + OFF_XS);
        const float* xbg = x + (size_t)(b * Cc + g * Dd) * HW;
        int lt = tid - 128;               // 0..127
        for (int idx = lt; idx < Dd * XDY * XDX; idx += 128) {
            int d  = idx / (XDY * XDX);
            int rr = idx - d * (XDY * XDX);
            int yy = rr / XDX;
            int xx = rr - yy * XDX;
            int gy = h0 + yy - Pp;
            int gx = w0 + xx - Pp;
            float v = 0.f;
            if (gy >= 0 && gy < Hh && gx >= 0 && gx < Ww)
                v = xbg[(size_t)d * HW + gy * Ww + gx];
            xs[(yy * XDX + xx) * XSTR + d] = v;
        }
    }
    __syncthreads();

    // ---- phase 2: involution, 256 threads, thread = 8px x 1d --------------------
    {
        int pg = tid >> 4;           // 0..15 pixel groups of 8
        int d  = tid & 15;
        int p0 = pg * 8;
        int y  = p0 >> 4;            // 0..7
        int x0 = p0 & 15;            // 0 or 8

        ull acc[4] = {0ull, 0ull, 0ull, 0ull};   // px pairs {0,1}{2,3}{4,5}{6,7}
        float cur[8];

#pragma unroll
        for (int ki = 0; ki < 7; ki++) {
            uint32_t rowa = sb + OFF_XS + (((y + ki) * XDX + x0) * XSTR + d) * 4;
#pragma unroll
            for (int p = 0; p < 7; p++)
                LDS32(cur[p], rowa + p * (XSTR * 4));
#pragma unroll
            for (int kj = 0; kj < 7; kj++) {
                LDS32(cur[(kj + 7) & 7], rowa + (kj + 7) * (XSTR * 4));
                uint32_t ka = sb + OFF_KER + ((ki * 7 + kj) * KST + p0) * 4;
                ull k01, k23, k45, k67;
                LDSV2(k01, k23, ka);
                LDSV2(k45, k67, ka + 16);
                ull a01, a23, a45, a67;
                PACK2(a01, cur[(kj + 0) & 7], cur[(kj + 1) & 7]);
                PACK2(a23, cur[(kj + 2) & 7], cur[(kj + 3) & 7]);
                PACK2(a45, cur[(kj + 4) & 7], cur[(kj + 5) & 7]);
                PACK2(a67, cur[(kj + 6) & 7], cur[(kj + 7) & 7]);
                FMA2(acc[0], a01, k01);
                FMA2(acc[1], a23, k23);
                FMA2(acc[2], a45, k45);
                FMA2(acc[3], a67, k67);
            }
        }

        float o[8];
        UNPACK2(o[0], o[1], acc[0]);
        UNPACK2(o[2], o[3], acc[1]);
        UNPACK2(o[4], o[5], acc[2]);
        UNPACK2(o[6], o[7], acc[3]);
        float* ob = out + (size_t)(b * Cc + g * Dd + d) * HW + (h0 + y) * Ww + w0 + x0;
        *(float4*)ob       = make_float4(o[0], o[1], o[2], o[3]);
        *(float4*)(ob + 4) = make_float4(o[4], o[5], o[6], o[7]);
    }
}

// ---------------- launcher -----------------------------------------------------
extern "C" void kernel_launch(void* const* d_in, const int* in_sizes, int n_in,
                              void* d_out, int out_size) {
    const float* x        = (const float*)d_in[0];
    const float* v_reduce = (const float*)d_in[1];
    const float* g_reduce = (const float*)d_in[2];
    const float* b_reduce = (const float*)d_in[3];
    const float* bn_gamma = (const float*)d_in[4];
    const float* bn_beta  = (const float*)d_in[5];
    const float* bn_mean  = (const float*)d_in[6];
    const float* bn_var   = (const float*)d_in[7];
    const float* v_span   = (const float*)d_in[8];
    const float* g_span   = (const float*)d_in[9];
    const float* b_span   = (const float*)d_in[10];
    float* out = (float*)d_out;

    static bool attr_set = false;
    if (!attr_set) {
        cudaFuncSetAttribute(fused_kernel,
                             cudaFuncAttributeMaxDynamicSharedMemorySize, SMEM_REQ);
        attr_set = true;
    }

    prep_weights<<<112, 256>>>(v_reduce, g_reduce, b_reduce,
                               bn_gamma, bn_beta, bn_mean, bn_var,
                               v_span, g_span, b_span);

    reduce_gemm<<<dim3(HW / 128, 1, Bb), 256>>>(x);

    fused_kernel<<<dim3(Ww / TSX, Hh / TSY, Bb * Gg), 256, SMEM_REQ>>>(x, out);
}

// round 8
// speedup vs baseline: 1.0111x; 1.0111x over previous
#include <cuda_runtime.h>
#include <math.h>
#include <stdint.h>

#define Bb   8
#define Cc   256
#define Hh   64
#define Ww   64
#define Gg   16
#define Dd   16
#define Pp   3
#define CRr  64
#define NT   49
#define NTP  52        // taps padded: 4 warps * 13
#define TPW  13
#define KKG  784
#define HW   4096
#define EPSf 1e-5f

// ---------------- packed f32x2 helpers ---------------------------------------
typedef unsigned long long ull;
#define FMA2(acc, a, b) asm("fma.rn.f32x2 %0, %1, %2, %0;" : "+l"(acc) : "l"(a), "l"(b))
#define ADD2(acc, a)    asm("add.rn.f32x2 %0, %0, %1;"     : "+l"(acc) : "l"(a))
#define PACK2(d, lo, hi) asm("mov.b64 %0, {%1, %2};" : "=l"(d) : "f"(lo), "f"(hi))
#define UNPACK2(lo, hi, s) asm("mov.b64 {%0, %1}, %2;" : "=f"(lo), "=f"(hi) : "l"(s))
#define LDSV2(lo, hi, addr) \
    asm volatile("ld.shared.v2.u64 {%0, %1}, [%2];" : "=l"(lo), "=l"(hi) : "r"(addr))
#define STSV2(addr, lo, hi) \
    asm volatile("st.shared.v2.u64 [%0], {%1, %2};" :: "r"(addr), "l"(lo), "l"(hi))
#define LDS64(dst, addr) \
    asm volatile("ld.shared.b64 %0, [%1];" : "=l"(dst) : "r"(addr))

static __device__ __forceinline__ uint32_t saddr(const void* p) {
    return (uint32_t)__cvta_generic_to_shared(p);
}

// ---------------- device-global scratch --------------------------------------
__device__ float g_wrT[Cc * CRr];                        // reduce weights [k][m]
__device__ float g_br[CRr];
__device__ __align__(16) float g_ws4[Gg * 32 * NTP * 4]; // [g][k2][tap]{wk,wk,wk1,wk1}
__device__ float g_bsp[KKG];
__device__ float g_r[(size_t)Bb * CRr * HW];             // reduce output [b][c][hw]

// ---------------- weight preparation (warp per row) ---------------------------
__global__ __launch_bounds__(256) void prep_weights(
        const float* __restrict__ v_reduce, const float* __restrict__ g_reduce,
        const float* __restrict__ b_reduce, const float* __restrict__ bn_gamma,
        const float* __restrict__ bn_beta,  const float* __restrict__ bn_mean,
        const float* __restrict__ bn_var,   const float* __restrict__ v_span,
        const float* __restrict__ g_span,   const float* __restrict__ b_span) {
    int row  = blockIdx.x * 8 + (threadIdx.x >> 5);
    int lane = threadIdx.x & 31;
    if (row < CRr) {
        float v[8];
        float s = 0.f;
#pragma unroll
        for (int i = 0; i < 8; i++) {
            v[i] = v_reduce[row * Cc + lane + i * 32];
            s += v[i] * v[i];
        }
#pragma unroll
        for (int off = 16; off > 0; off >>= 1)
            s += __shfl_xor_sync(0xffffffffu, s, off);
        float scale = bn_gamma[row] * rsqrtf(bn_var[row] + EPSf);
        float wmul  = g_reduce[row] / sqrtf(s) * scale;
#pragma unroll
        for (int i = 0; i < 8; i++)
            g_wrT[(lane + i * 32) * CRr + row] = v[i] * wmul;
        if (lane == 0)
            g_br[row] = (b_reduce[row] - bn_mean[row]) * scale + bn_beta[row];
    } else if (row < CRr + KKG) {
        int o = row - CRr;            // o = tap*16 + g
        int tap = o >> 4;
        int gq  = o & 15;
        float v0 = v_span[o * CRr + lane];
        float v1 = v_span[o * CRr + 32 + lane];
        float s = v0 * v0 + v1 * v1;
#pragma unroll
        for (int off = 16; off > 0; off >>= 1)
            s += __shfl_xor_sync(0xffffffffu, s, off);
        float wmul = g_span[o] / sqrtf(s);
        float w0 = v0 * wmul, w1 = v1 * wmul;
        int c0 = lane, c1 = lane + 32;
        int i0 = ((gq * 32 + (c0 >> 1)) * NTP + tap) * 4 + (c0 & 1) * 2;
        int i1 = ((gq * 32 + (c1 >> 1)) * NTP + tap) * 4 + (c1 & 1) * 2;
        g_ws4[i0] = w0; g_ws4[i0 + 1] = w0;
        g_ws4[i1] = w1; g_ws4[i1 + 1] = w1;
        if (lane == 0) g_bsp[o] = b_span[o];
    } else if (row < CRr + KKG + Gg * 3) {
        int p = row - (CRr + KKG);    // zero-pad taps 49..51
        int gq = p / 3;
        int tap = NT + p % 3;
        int c0 = lane, c1 = lane + 32;
        int i0 = ((gq * 32 + (c0 >> 1)) * NTP + tap) * 4 + (c0 & 1) * 2;
        int i1 = ((gq * 32 + (c1 >> 1)) * NTP + tap) * 4 + (c1 & 1) * 2;
        g_ws4[i0] = 0.f; g_ws4[i0 + 1] = 0.f;
        g_ws4[i1] = 0.f; g_ws4[i1 + 1] = 0.f;
    }
}

// ---------------- reduce GEMM: m=64 x n=128 px, 256 CTAs ----------------------
__global__ __launch_bounds__(256) void reduce_gemm(const float* __restrict__ x) {
    __shared__ float As[16][64];
    __shared__ float Bs[16][128];
    int b  = blockIdx.z;
    int n0 = blockIdx.x * 128;
    int tid = threadIdx.x;
    int ty = tid >> 5;
    int tx = tid & 31;
    const float* xb = x + (size_t)b * Cc * HW;

    ull acc2[4][4];
#pragma unroll
    for (int i = 0; i < 4; i++)
#pragma unroll
        for (int j = 0; j < 4; j++) acc2[i][j] = 0ull;

    for (int k0 = 0; k0 < Cc; k0 += 16) {
        {
            int kr = tid >> 4, m4 = (tid & 15) * 4;
            *(float4*)&As[kr][m4] = *(const float4*)&g_wrT[(k0 + kr) * CRr + m4];
        }
#pragma unroll
        for (int q = 0; q < 2; q++) {
            int f = q * 256 + tid;
            int kr = f >> 5, c4 = (f & 31) * 4;
            *(float4*)&Bs[kr][c4] = *(const float4*)(xb + (size_t)(k0 + kr) * HW + n0 + c4);
        }
        __syncthreads();
#pragma unroll
        for (int k = 0; k < 16; k++) {
            ull a0, a1, a2, a3;
            LDSV2(a0, a1, saddr(&As[k][ty * 8]));
            LDSV2(a2, a3, saddr(&As[k][ty * 8 + 4]));
            float4 bv = *(float4*)&Bs[k][tx * 4];
            float bs[4] = {bv.x, bv.y, bv.z, bv.w};
            ull bd[4];
#pragma unroll
            for (int j = 0; j < 4; j++) PACK2(bd[j], bs[j], bs[j]);
            ull aa[4] = {a0, a1, a2, a3};
#pragma unroll
            for (int i = 0; i < 4; i++)
#pragma unroll
                for (int j = 0; j < 4; j++)
                    FMA2(acc2[i][j], aa[i], bd[j]);
        }
        __syncthreads();
    }

    float bia[8];
#pragma unroll
    for (int i = 0; i < 8; i++) bia[i] = g_br[ty * 8 + i];
    float* rb = g_r + (size_t)b * CRr * HW;
#pragma unroll
    for (int i = 0; i < 4; i++) {
        float f[2][4];
#pragma unroll
        for (int j = 0; j < 4; j++) {
            float lo, hi;
            UNPACK2(lo, hi, acc2[i][j]);
            f[0][j] = fmaxf(lo + bia[2 * i], 0.f);
            f[1][j] = fmaxf(hi + bia[2 * i + 1], 0.f);
        }
#pragma unroll
        for (int h = 0; h < 2; h++) {
            int m = ty * 8 + 2 * i + h;
            *(float4*)(rb + (size_t)m * HW + n0 + tx * 4) =
                make_float4(f[h][0], f[h][1], f[h][2], f[h][3]);
        }
    }
}

// ---------------- fused span + involution (8x16 tile, 2 CTAs/SM) --------------
#define TSX  16
#define TSY  8
#define NPX  128
#define XDX  22
#define XDY  14
#define XSTR 20
#define KST  132
#define OFF_RS   0                      // 64k x 128px fp32   = 32768 B
#define OFF_WS   32768                  // 32 x 52 x 16B      = 26624 B
#define OFF_XS   59392                  // 308 x 20 x 4       = 24640 B
#define OFF_KER  84032                  // 49 x 132 x 4       = 25872 B
#define OFF_BS   109904                 // 52 x 4
#define SMEM_REQ 110112

extern __shared__ char smraw[];

__global__ __launch_bounds__(256, 2) void fused_kernel(
        const float* __restrict__ x, float* __restrict__ out) {
    int tid  = threadIdx.x;
    int wid  = tid >> 5;
    int lane = tid & 31;
    int bz = blockIdx.z;
    int b = bz >> 4, g = bz & 15;
    int h0 = blockIdx.y * TSY, w0 = blockIdx.x * TSX;
    uint32_t sb = saddr(smraw);

    // ---- cooperative loads: rs + ws + bias --------------------------------------
    {
        const float* rb = g_r + (size_t)b * CRr * HW;
        float* rs = (float*)(smraw + OFF_RS);
#pragma unroll
        for (int it = 0; it < 8; it++) {
            int i = tid + it * 256;          // 2048 float4
            int c = i >> 5, rem = i & 31;
            int y = rem >> 2, x4 = (rem & 3) << 2;
            float4 v = *(const float4*)(rb + (size_t)c * HW + (h0 + y) * Ww + w0 + x4);
            *(float4*)(rs + c * NPX + y * 16 + x4) = v;
        }
    }
    {
        const uint4* src = (const uint4*)g_ws4 + (size_t)g * (32 * NTP);
        uint4* dst = (uint4*)(smraw + OFF_WS);
#pragma unroll
        for (int it = 0; it < 7; it++) {
            int i = tid + it * 256;
            if (i < 32 * NTP) dst[i] = src[i];
        }
    }
    if (tid < NTP)
        ((float*)(smraw + OFF_BS))[tid] = (tid < NT) ? g_bsp[tid * Gg + g] : 0.f;
    __syncthreads();

    // ---- phase 1: warps 0-3 (13 taps each) | warps 4-7 load x halo -------------
    if (wid < 4) {
        ull acc2[TPW][2];
#pragma unroll
        for (int i = 0; i < TPW; i++) { acc2[i][0] = 0ull; acc2[i][1] = 0ull; }

        uint32_t rs_a = sb + OFF_RS + lane * 16;
        uint32_t ws_a = sb + OFF_WS + wid * TPW * 16;
#pragma unroll 2
        for (int k2 = 0; k2 < 32; k2++) {
            ull b0, b1, c0, c1;
            uint32_t ra = rs_a + k2 * 1024;
            LDSV2(b0, b1, ra);            // k even : px {0,1},{2,3}
            LDSV2(c0, c1, ra + 512);      // k odd
            uint32_t wa = ws_a + k2 * (NTP * 16);
#pragma unroll
            for (int i = 0; i < TPW; i++) {
                ull a0, a1;
                LDSV2(a0, a1, wa + i * 16);
                FMA2(acc2[i][0], a0, b0);
                FMA2(acc2[i][1], a0, b1);
                FMA2(acc2[i][0], a1, c0);
                FMA2(acc2[i][1], a1, c1);
            }
        }
        float* bs = (float*)(smraw + OFF_BS);
#pragma unroll
        for (int i = 0; i < TPW; i++) {
            int tap = wid * TPW + i;
            if (tap < NT) {
                ull bp;
                float bv = bs[tap];
                PACK2(bp, bv, bv);
                ADD2(acc2[i][0], bp);
                ADD2(acc2[i][1], bp);
                STSV2(sb + OFF_KER + tap * (KST * 4) + lane * 16,
                      acc2[i][0], acc2[i][1]);
            }
        }
    } else {
        float* xs = (float*)(smraw + OFF_XS);
        const float* xbg = x + (size_t)(b * Cc + g * Dd) * HW;
        int lt = tid - 128;               // 0..127
        for (int idx = lt; idx < Dd * XDY * XDX; idx += 128) {
            int d  = idx / (XDY * XDX);
            int rr = idx - d * (XDY * XDX);
            int yy = rr / XDX;
            int xx = rr - yy * XDX;
            int gy = h0 + yy - Pp;
            int gx = w0 + xx - Pp;
            float v = 0.f;
            if (gy >= 0 && gy < Hh && gx >= 0 && gx < Ww)
                v = xbg[(size_t)d * HW + gy * Ww + gx];
            xs[(yy * XDX + xx) * XSTR + d] = v;
        }
    }
    __syncthreads();

    // ---- phase 2: involution, all 8 warps, thread = 4px x 2d --------------------
    {
        float* kerp = (float*)(smraw + OFF_KER);
        int pg = tid >> 3;          // 32 pixel groups of 4
        int dp = tid & 7;           // d-pair index
        int p0 = pg * 4;
        int y  = p0 >> 4;           // 0..7
        int x0 = p0 & 15;           // 0,4,8,12
        int d0 = dp * 2;

        ull accb[4] = {0ull, 0ull, 0ull, 0ull};   // px 0..3, one d-pair

        uint32_t xs_a = sb + OFF_XS;
#pragma unroll
        for (int ki = 0; ki < 7; ki++) {
            uint32_t xrow = xs_a + (((y + ki) * XDX + x0) * XSTR + d0) * 4;
            ull cur[4];
#pragma unroll
            for (int p = 0; p < 3; p++)
                LDS64(cur[p], xrow + p * (XSTR * 4));
#pragma unroll
            for (int kj = 0; kj < 7; kj++) {
                {
                    int s = (kj + 3) & 3;
                    LDS64(cur[s], xrow + (kj + 3) * (XSTR * 4));
                }
                float4 kv = *(float4*)(kerp + (ki * 7 + kj) * KST + p0);
                float kvv[4] = {kv.x, kv.y, kv.z, kv.w};
                ull kd[4];
#pragma unroll
                for (int px = 0; px < 4; px++) PACK2(kd[px], kvv[px], kvv[px]);
#pragma unroll
                for (int px = 0; px < 4; px++) {
                    int s = (kj + px) & 3;
                    FMA2(accb[px], cur[s], kd[px]);
                }
            }
        }

        // unpack: accb[px] = {d0, d0+1} at pixel px
        float lo[4], hi[4];
#pragma unroll
        for (int px = 0; px < 4; px++) UNPACK2(lo[px], hi[px], accb[px]);
        float* ob = out + (size_t)(b * Cc + g * Dd + d0) * HW + (h0 + y) * Ww + w0 + x0;
        *(float4*)ob                 = make_float4(lo[0], lo[1], lo[2], lo[3]);
        *(float4*)(ob + (size_t)HW)  = make_float4(hi[0], hi[1], hi[2], hi[3]);
    }
}

// ---------------- launcher -----------------------------------------------------
extern "C" void kernel_launch(void* const* d_in, const int* in_sizes, int n_in,
                              void* d_out, int out_size) {
    const float* x        = (const float*)d_in[0];
    const float* v_reduce = (const float*)d_in[1];
    const float* g_reduce = (const float*)d_in[2];
    const float* b_reduce = (const float*)d_in[3];
    const float* bn_gamma = (const float*)d_in[4];
    const float* bn_beta  = (const float*)d_in[5];
    const float* bn_mean  = (const float*)d_in[6];
    const float* bn_var   = (const float*)d_in[7];
    const float* v_span   = (const float*)d_in[8];
    const float* g_span   = (const float*)d_in[9];
    const float* b_span   = (const float*)d_in[10];
    float* out = (float*)d_out;

    static bool attr_set = false;
    if (!attr_set) {
        cudaFuncSetAttribute(fused_kernel,
                             cudaFuncAttributeMaxDynamicSharedMemorySize, SMEM_REQ);
        attr_set = true;
    }

    prep_weights<<<112, 256>>>(v_reduce, g_reduce, b_reduce,
                               bn_gamma, bn_beta, bn_mean, bn_var,
                               v_span, g_span, b_span);

    reduce_gemm<<<dim3(HW / 128, 1, Bb), 256>>>(x);

    fused_kernel<<<dim3(Ww / TSX, Hh / TSY, Bb * Gg), 256, SMEM_REQ>>>(x, out);
}

// round 9
// speedup vs baseline: 1.0702x; 1.0585x over previous
#include <cuda_runtime.h>
#include <math.h>
#include <stdint.h>

#define Bb   8
#define Cc   256
#define Hh   64
#define Ww   64
#define Gg   16
#define Dd   16
#define Pp   3
#define CRr  64
#define NT   49
#define NTP  52        // taps padded: 4 warps * 13
#define TPW  13
#define KKG  784
#define HW   4096
#define EPSf 1e-5f

// ---------------- packed f32x2 helpers ---------------------------------------
typedef unsigned long long ull;
#define FMA2(acc, a, b) asm("fma.rn.f32x2 %0, %1, %2, %0;" : "+l"(acc) : "l"(a), "l"(b))
#define ADD2(acc, a)    asm("add.rn.f32x2 %0, %0, %1;"     : "+l"(acc) : "l"(a))
#define PACK2(d, lo, hi) asm("mov.b64 %0, {%1, %2};" : "=l"(d) : "f"(lo), "f"(hi))
#define UNPACK2(lo, hi, s) asm("mov.b64 {%0, %1}, %2;" : "=f"(lo), "=f"(hi) : "l"(s))
#define LDSV2(lo, hi, addr) \
    asm volatile("ld.shared.v2.u64 {%0, %1}, [%2];" : "=l"(lo), "=l"(hi) : "r"(addr))
#define STSV2(addr, lo, hi) \
    asm volatile("st.shared.v2.u64 [%0], {%1, %2};" :: "r"(addr), "l"(lo), "l"(hi))

static __device__ __forceinline__ uint32_t saddr(const void* p) {
    return (uint32_t)__cvta_generic_to_shared(p);
}

// ---------------- device-global scratch --------------------------------------
__device__ float g_wrT[Cc * CRr];                        // reduce weights [k][m]
__device__ float g_br[CRr];
__device__ __align__(16) float g_ws4[Gg * 32 * NTP * 4]; // [g][k2][tap]{wk,wk,wk1,wk1}
__device__ float g_bsp[KKG];
__device__ float g_r[(size_t)Bb * CRr * HW];             // reduce output [b][c][hw]

// ---------------- weight preparation (warp per row) ---------------------------
__global__ __launch_bounds__(256) void prep_weights(
        const float* __restrict__ v_reduce, const float* __restrict__ g_reduce,
        const float* __restrict__ b_reduce, const float* __restrict__ bn_gamma,
        const float* __restrict__ bn_beta,  const float* __restrict__ bn_mean,
        const float* __restrict__ bn_var,   const float* __restrict__ v_span,
        const float* __restrict__ g_span,   const float* __restrict__ b_span) {
    int row  = blockIdx.x * 8 + (threadIdx.x >> 5);
    int lane = threadIdx.x & 31;
    if (row < CRr) {
        float v[8];
        float s = 0.f;
#pragma unroll
        for (int i = 0; i < 8; i++) {
            v[i] = v_reduce[row * Cc + lane + i * 32];
            s += v[i] * v[i];
        }
#pragma unroll
        for (int off = 16; off > 0; off >>= 1)
            s += __shfl_xor_sync(0xffffffffu, s, off);
        float scale = bn_gamma[row] * rsqrtf(bn_var[row] + EPSf);
        float wmul  = g_reduce[row] / sqrtf(s) * scale;
#pragma unroll
        for (int i = 0; i < 8; i++)
            g_wrT[(lane + i * 32) * CRr + row] = v[i] * wmul;
        if (lane == 0)
            g_br[row] = (b_reduce[row] - bn_mean[row]) * scale + bn_beta[row];
    } else if (row < CRr + KKG) {
        int o = row - CRr;            // o = tap*16 + g
        int tap = o >> 4;
        int gq  = o & 15;
        float v0 = v_span[o * CRr + lane];
        float v1 = v_span[o * CRr + 32 + lane];
        float s = v0 * v0 + v1 * v1;
#pragma unroll
        for (int off = 16; off > 0; off >>= 1)
            s += __shfl_xor_sync(0xffffffffu, s, off);
        float wmul = g_span[o] / sqrtf(s);
        float w0 = v0 * wmul, w1 = v1 * wmul;
        int c0 = lane, c1 = lane + 32;
        int i0 = ((gq * 32 + (c0 >> 1)) * NTP + tap) * 4 + (c0 & 1) * 2;
        int i1 = ((gq * 32 + (c1 >> 1)) * NTP + tap) * 4 + (c1 & 1) * 2;
        g_ws4[i0] = w0; g_ws4[i0 + 1] = w0;
        g_ws4[i1] = w1; g_ws4[i1 + 1] = w1;
        if (lane == 0) g_bsp[o] = b_span[o];
    } else if (row < CRr + KKG + Gg * 3) {
        int p = row - (CRr + KKG);    // zero-pad taps 49..51
        int gq = p / 3;
        int tap = NT + p % 3;
        int c0 = lane, c1 = lane + 32;
        int i0 = ((gq * 32 + (c0 >> 1)) * NTP + tap) * 4 + (c0 & 1) * 2;
        int i1 = ((gq * 32 + (c1 >> 1)) * NTP + tap) * 4 + (c1 & 1) * 2;
        g_ws4[i0] = 0.f; g_ws4[i0 + 1] = 0.f;
        g_ws4[i1] = 0.f; g_ws4[i1 + 1] = 0.f;
    }
}

// ---------------- reduce GEMM: m=64 x n=128 px, 256 CTAs ----------------------
__global__ __launch_bounds__(256) void reduce_gemm(const float* __restrict__ x) {
    __shared__ float As[16][64];
    __shared__ float Bs[16][128];
    int b  = blockIdx.z;
    int n0 = blockIdx.x * 128;
    int tid = threadIdx.x;
    int ty = tid >> 5;
    int tx = tid & 31;
    const float* xb = x + (size_t)b * Cc * HW;

    ull acc2[4][4];
#pragma unroll
    for (int i = 0; i < 4; i++)
#pragma unroll
        for (int j = 0; j < 4; j++) acc2[i][j] = 0ull;

    for (int k0 = 0; k0 < Cc; k0 += 16) {
        {
            int kr = tid >> 4, m4 = (tid & 15) * 4;
            *(float4*)&As[kr][m4] = *(const float4*)&g_wrT[(k0 + kr) * CRr + m4];
        }
#pragma unroll
        for (int q = 0; q < 2; q++) {
            int f = q * 256 + tid;
            int kr = f >> 5, c4 = (f & 31) * 4;
            *(float4*)&Bs[kr][c4] = *(const float4*)(xb + (size_t)(k0 + kr) * HW + n0 + c4);
        }
        __syncthreads();
#pragma unroll
        for (int k = 0; k < 16; k++) {
            ull a0, a1, a2, a3;
            LDSV2(a0, a1, saddr(&As[k][ty * 8]));
            LDSV2(a2, a3, saddr(&As[k][ty * 8 + 4]));
            float4 bv = *(float4*)&Bs[k][tx * 4];
            float bs[4] = {bv.x, bv.y, bv.z, bv.w};
            ull bd[4];
#pragma unroll
            for (int j = 0; j < 4; j++) PACK2(bd[j], bs[j], bs[j]);
            ull aa[4] = {a0, a1, a2, a3};
#pragma unroll
            for (int i = 0; i < 4; i++)
#pragma unroll
                for (int j = 0; j < 4; j++)
                    FMA2(acc2[i][j], aa[i], bd[j]);
        }
        __syncthreads();
    }

    float bia[8];
#pragma unroll
    for (int i = 0; i < 8; i++) bia[i] = g_br[ty * 8 + i];
    float* rb = g_r + (size_t)b * CRr * HW;
#pragma unroll
    for (int i = 0; i < 4; i++) {
        float f[2][4];
#pragma unroll
        for (int j = 0; j < 4; j++) {
            float lo, hi;
            UNPACK2(lo, hi, acc2[i][j]);
            f[0][j] = fmaxf(lo + bia[2 * i], 0.f);
            f[1][j] = fmaxf(hi + bia[2 * i + 1], 0.f);
        }
#pragma unroll
        for (int h = 0; h < 2; h++) {
            int m = ty * 8 + 2 * i + h;
            *(float4*)(rb + (size_t)m * HW + n0 + tx * 4) =
                make_float4(f[h][0], f[h][1], f[h][2], f[h][3]);
        }
    }
}

// ---------------- fused span + involution (8x16 tile, 2 CTAs/SM) --------------
// (round-6 structure verbatim)
#define TSX  16
#define TSY  8
#define NPX  128
#define XDX  22
#define XDY  14
#define XSTR 20
#define KST  132
#define OFF_RS   0                      // 64k x 128px fp32   = 32768 B
#define OFF_WS   32768                  // 32 x 52 x 16B      = 26624 B
#define OFF_XS   59392                  // 308 x 20 x 4       = 24640 B
#define OFF_KER  84032                  // 49 x 132 x 4       = 25872 B
#define OFF_BS   109904                 // 52 x 4
#define SMEM_REQ 110112

extern __shared__ char smraw[];

__global__ __launch_bounds__(256, 2) void fused_kernel(
        const float* __restrict__ x, float* __restrict__ out) {
    int tid  = threadIdx.x;
    int wid  = tid >> 5;
    int lane = tid & 31;
    int bz = blockIdx.z;
    int b = bz >> 4, g = bz & 15;
    int h0 = blockIdx.y * TSY, w0 = blockIdx.x * TSX;
    uint32_t sb = saddr(smraw);

    // ---- cooperative loads: rs + ws + bias --------------------------------------
    {
        const float* rb = g_r + (size_t)b * CRr * HW;
        float* rs = (float*)(smraw + OFF_RS);
#pragma unroll
        for (int it = 0; it < 8; it++) {
            int i = tid + it * 256;          // 2048 float4
            int c = i >> 5, rem = i & 31;
            int y = rem >> 2, x4 = (rem & 3) << 2;
            float4 v = *(const float4*)(rb + (size_t)c * HW + (h0 + y) * Ww + w0 + x4);
            *(float4*)(rs + c * NPX + y * 16 + x4) = v;
        }
    }
    {
        const uint4* src = (const uint4*)g_ws4 + (size_t)g * (32 * NTP);
        uint4* dst = (uint4*)(smraw + OFF_WS);
#pragma unroll
        for (int it = 0; it < 7; it++) {
            int i = tid + it * 256;
            if (i < 32 * NTP) dst[i] = src[i];
        }
    }
    if (tid < NTP)
        ((float*)(smraw + OFF_BS))[tid] = (tid < NT) ? g_bsp[tid * Gg + g] : 0.f;
    __syncthreads();

    // ---- phase 1: warps 0-3 (13 taps each) | warps 4-7 load x halo -------------
    if (wid < 4) {
        ull acc2[TPW][2];
#pragma unroll
        for (int i = 0; i < TPW; i++) { acc2[i][0] = 0ull; acc2[i][1] = 0ull; }

        uint32_t rs_a = sb + OFF_RS + lane * 16;
        uint32_t ws_a = sb + OFF_WS + wid * TPW * 16;
#pragma unroll 2
        for (int k2 = 0; k2 < 32; k2++) {
            ull b0, b1, c0, c1;
            uint32_t ra = rs_a + k2 * 1024;
            LDSV2(b0, b1, ra);            // k even : px {0,1},{2,3}
            LDSV2(c0, c1, ra + 512);      // k odd
            uint32_t wa = ws_a + k2 * (NTP * 16);
#pragma unroll
            for (int i = 0; i < TPW; i++) {
                ull a0, a1;
                LDSV2(a0, a1, wa + i * 16);
                FMA2(acc2[i][0], a0, b0);
                FMA2(acc2[i][1], a0, b1);
                FMA2(acc2[i][0], a1, c0);
                FMA2(acc2[i][1], a1, c1);
            }
        }
        float* bs = (float*)(smraw + OFF_BS);
#pragma unroll
        for (int i = 0; i < TPW; i++) {
            int tap = wid * TPW + i;
            if (tap < NT) {
                ull bp;
                float bv = bs[tap];
                PACK2(bp, bv, bv);
                ADD2(acc2[i][0], bp);
                ADD2(acc2[i][1], bp);
                STSV2(sb + OFF_KER + tap * (KST * 4) + lane * 16,
                      acc2[i][0], acc2[i][1]);
            }
        }
    } else {
        float* xs = (float*)(smraw + OFF_XS);
        const float* xbg = x + (size_t)(b * Cc + g * Dd) * HW;
        int lt = tid - 128;               // 0..127
        for (int idx = lt; idx < Dd * XDY * XDX; idx += 128) {
            int d  = idx / (XDY * XDX);
            int rr = idx - d * (XDY * XDX);
            int yy = rr / XDX;
            int xx = rr - yy * XDX;
            int gy = h0 + yy - Pp;
            int gx = w0 + xx - Pp;
            float v = 0.f;
            if (gy >= 0 && gy < Hh && gx >= 0 && gx < Ww)
                v = xbg[(size_t)d * HW + gy * Ww + gx];
            xs[(yy * XDX + xx) * XSTR + d] = v;
        }
    }
    __syncthreads();

    // ---- phase 2: involution (warps 0-3: 4px x 4d sliding window) --------------
    if (wid < 4) {
        float* kerp = (float*)(smraw + OFF_KER);
        int pg = tid >> 2;          // 32 pixel groups of 4
        int dq = tid & 3;
        int p0 = pg * 4;
        int y  = p0 >> 4;           // 0..7
        int x0 = p0 & 15;           // 0,4,8,12
        int d0 = dq * 4;

        ull accb[2][4];             // [d-pair][px]
#pragma unroll
        for (int dp = 0; dp < 2; dp++)
#pragma unroll
            for (int px = 0; px < 4; px++) accb[dp][px] = 0ull;

        uint32_t xs_a = sb + OFF_XS;
#pragma unroll
        for (int ki = 0; ki < 7; ki++) {
            uint32_t xrow = xs_a + (((y + ki) * XDX + x0) * XSTR + d0) * 4;
            ull cur[4][2];
#pragma unroll
            for (int p = 0; p < 3; p++)
                LDSV2(cur[p][0], cur[p][1], xrow + p * (XSTR * 4));
#pragma unroll
            for (int kj = 0; kj < 7; kj++) {
                {
                    int s = (kj + 3) & 3;
                    LDSV2(cur[s][0], cur[s][1], xrow + (kj + 3) * (XSTR * 4));
                }
                float4 kv = *(float4*)(kerp + (ki * 7 + kj) * KST + p0);
                float kvv[4] = {kv.x, kv.y, kv.z, kv.w};
                ull kd[4];
#pragma unroll
                for (int px = 0; px < 4; px++) PACK2(kd[px], kvv[px], kvv[px]);
#pragma unroll
                for (int px = 0; px < 4; px++) {
                    int s = (kj + px) & 3;
                    FMA2(accb[0][px], cur[s][0], kd[px]);
                    FMA2(accb[1][px], cur[s][1], kd[px]);
                }
            }
        }

        float* ob = out + (size_t)(b * Cc + g * Dd + d0) * HW + (h0 + y) * Ww + w0 + x0;
#pragma unroll
        for (int dp = 0; dp < 2; dp++) {
            float lo[4], hi[4];
#pragma unroll
            for (int px = 0; px < 4; px++) UNPACK2(lo[px], hi[px], accb[dp][px]);
            *(float4*)(ob + (size_t)(2 * dp) * HW)     = make_float4(lo[0], lo[1], lo[2], lo[3]);
            *(float4*)(ob + (size_t)(2 * dp + 1) * HW) = make_float4(hi[0], hi[1], hi[2], hi[3]);
        }
    }
}

// ---------------- launcher -----------------------------------------------------
extern "C" void kernel_launch(void* const* d_in, const int* in_sizes, int n_in,
                              void* d_out, int out_size) {
    const float* x        = (const float*)d_in[0];
    const float* v_reduce = (const float*)d_in[1];
    const float* g_reduce = (const float*)d_in[2];
    const float* b_reduce = (const float*)d_in[3];
    const float* bn_gamma = (const float*)d_in[4];
    const float* bn_beta  = (const float*)d_in[5];
    const float* bn_mean  = (const float*)d_in[6];
    const float* bn_var   = (const float*)d_in[7];
    const float* v_span   = (const float*)d_in[8];
    const float* g_span   = (const float*)d_in[9];
    const float* b_span   = (const float*)d_in[10];
    float* out = (float*)d_out;

    static bool attr_set = false;
    if (!attr_set) {
        cudaFuncSetAttribute(fused_kernel,
                             cudaFuncAttributeMaxDynamicSharedMemorySize, SMEM_REQ);
        attr_set = true;
    }

    prep_weights<<<112, 256>>>(v_reduce, g_reduce, b_reduce,
                               bn_gamma, bn_beta, bn_mean, bn_var,
                               v_span, g_span, b_span);

    reduce_gemm<<<dim3(HW / 128, 1, Bb), 256>>>(x);

    fused_kernel<<<dim3(Ww / TSX, Hh / TSY, Bb * Gg), 256, SMEM_REQ>>>(x, out);
}

// round 10
// speedup vs baseline: 1.0726x; 1.0022x over previous
#include <cuda_runtime.h>
#include <math.h>
#include <stdint.h>

#define Bb   8
#define Cc   256
#define Hh   64
#define Ww   64
#define Gg   16
#define Dd   16
#define Pp   3
#define CRr  64
#define NT   49
#define NTP  52        // taps padded: 4 warps * 13
#define TPW  13
#define KKG  784
#define HW   4096
#define EPSf 1e-5f

// ---------------- packed f32x2 helpers ---------------------------------------
typedef unsigned long long ull;
#define FMA2(acc, a, b) asm("fma.rn.f32x2 %0, %1, %2, %0;" : "+l"(acc) : "l"(a), "l"(b))
#define ADD2(acc, a)    asm("add.rn.f32x2 %0, %0, %1;"     : "+l"(acc) : "l"(a))
#define PACK2(d, lo, hi) asm("mov.b64 %0, {%1, %2};" : "=l"(d) : "f"(lo), "f"(hi))
#define UNPACK2(lo, hi, s) asm("mov.b64 {%0, %1}, %2;" : "=f"(lo), "=f"(hi) : "l"(s))
#define LDSV2(lo, hi, addr) \
    asm volatile("ld.shared.v2.u64 {%0, %1}, [%2];" : "=l"(lo), "=l"(hi) : "r"(addr))
#define STSV2(addr, lo, hi) \
    asm volatile("st.shared.v2.u64 [%0], {%1, %2};" :: "r"(addr), "l"(lo), "l"(hi))

static __device__ __forceinline__ uint32_t saddr(const void* p) {
    return (uint32_t)__cvta_generic_to_shared(p);
}

// ---------------- device-global scratch --------------------------------------
__device__ float g_wrT[Cc * CRr];                        // reduce weights [k][m]
__device__ float g_br[CRr];
__device__ __align__(16) float g_ws4[Gg * 32 * NTP * 4]; // [g][k2][tap]{wk,wk,wk1,wk1}
__device__ float g_bsp[KKG];
__device__ float g_r[(size_t)Bb * CRr * HW];             // reduce output [b][c][hw]

// ---------------- weight preparation (warp per row) ---------------------------
__global__ __launch_bounds__(256) void prep_weights(
        const float* __restrict__ v_reduce, const float* __restrict__ g_reduce,
        const float* __restrict__ b_reduce, const float* __restrict__ bn_gamma,
        const float* __restrict__ bn_beta,  const float* __restrict__ bn_mean,
        const float* __restrict__ bn_var,   const float* __restrict__ v_span,
        const float* __restrict__ g_span,   const float* __restrict__ b_span) {
    int row  = blockIdx.x * 8 + (threadIdx.x >> 5);
    int lane = threadIdx.x & 31;
    if (row < CRr) {
        float v[8];
        float s = 0.f;
#pragma unroll
        for (int i = 0; i < 8; i++) {
            v[i] = v_reduce[row * Cc + lane + i * 32];
            s += v[i] * v[i];
        }
#pragma unroll
        for (int off = 16; off > 0; off >>= 1)
            s += __shfl_xor_sync(0xffffffffu, s, off);
        float scale = bn_gamma[row] * rsqrtf(bn_var[row] + EPSf);
        float wmul  = g_reduce[row] / sqrtf(s) * scale;
#pragma unroll
        for (int i = 0; i < 8; i++)
            g_wrT[(lane + i * 32) * CRr + row] = v[i] * wmul;
        if (lane == 0)
            g_br[row] = (b_reduce[row] - bn_mean[row]) * scale + bn_beta[row];
    } else if (row < CRr + KKG) {
        int o = row - CRr;            // o = tap*16 + g
        int tap = o >> 4;
        int gq  = o & 15;
        float v0 = v_span[o * CRr + lane];
        float v1 = v_span[o * CRr + 32 + lane];
        float s = v0 * v0 + v1 * v1;
#pragma unroll
        for (int off = 16; off > 0; off >>= 1)
            s += __shfl_xor_sync(0xffffffffu, s, off);
        float wmul = g_span[o] / sqrtf(s);
        float w0 = v0 * wmul, w1 = v1 * wmul;
        int c0 = lane, c1 = lane + 32;
        int i0 = ((gq * 32 + (c0 >> 1)) * NTP + tap) * 4 + (c0 & 1) * 2;
        int i1 = ((gq * 32 + (c1 >> 1)) * NTP + tap) * 4 + (c1 & 1) * 2;
        g_ws4[i0] = w0; g_ws4[i0 + 1] = w0;
        g_ws4[i1] = w1; g_ws4[i1 + 1] = w1;
        if (lane == 0) g_bsp[o] = b_span[o];
    } else if (row < CRr + KKG + Gg * 3) {
        int p = row - (CRr + KKG);    // zero-pad taps 49..51
        int gq = p / 3;
        int tap = NT + p % 3;
        int c0 = lane, c1 = lane + 32;
        int i0 = ((gq * 32 + (c0 >> 1)) * NTP + tap) * 4 + (c0 & 1) * 2;
        int i1 = ((gq * 32 + (c1 >> 1)) * NTP + tap) * 4 + (c1 & 1) * 2;
        g_ws4[i0] = 0.f; g_ws4[i0 + 1] = 0.f;
        g_ws4[i1] = 0.f; g_ws4[i1 + 1] = 0.f;
    }
}

// ---------------- reduce GEMM: m=64 x n=128 px, 256 CTAs ----------------------
__global__ __launch_bounds__(256) void reduce_gemm(const float* __restrict__ x) {
    __shared__ float As[16][64];
    __shared__ float Bs[16][128];
    int b  = blockIdx.z;
    int n0 = blockIdx.x * 128;
    int tid = threadIdx.x;
    int ty = tid >> 5;
    int tx = tid & 31;
    const float* xb = x + (size_t)b * Cc * HW;

    ull acc2[4][4];
#pragma unroll
    for (int i = 0; i < 4; i++)
#pragma unroll
        for (int j = 0; j < 4; j++) acc2[i][j] = 0ull;

    for (int k0 = 0; k0 < Cc; k0 += 16) {
        {
            int kr = tid >> 4, m4 = (tid & 15) * 4;
            *(float4*)&As[kr][m4] = *(const float4*)&g_wrT[(k0 + kr) * CRr + m4];
        }
#pragma unroll
        for (int q = 0; q < 2; q++) {
            int f = q * 256 + tid;
            int kr = f >> 5, c4 = (f & 31) * 4;
            *(float4*)&Bs[kr][c4] = *(const float4*)(xb + (size_t)(k0 + kr) * HW + n0 + c4);
        }
        __syncthreads();
#pragma unroll
        for (int k = 0; k < 16; k++) {
            ull a0, a1, a2, a3;
            LDSV2(a0, a1, saddr(&As[k][ty * 8]));
            LDSV2(a2, a3, saddr(&As[k][ty * 8 + 4]));
            float4 bv = *(float4*)&Bs[k][tx * 4];
            float bs[4] = {bv.x, bv.y, bv.z, bv.w};
            ull bd[4];
#pragma unroll
            for (int j = 0; j < 4; j++) PACK2(bd[j], bs[j], bs[j]);
            ull aa[4] = {a0, a1, a2, a3};
#pragma unroll
            for (int i = 0; i < 4; i++)
#pragma unroll
                for (int j = 0; j < 4; j++)
                    FMA2(acc2[i][j], aa[i], bd[j]);
        }
        __syncthreads();
    }

    float bia[8];
#pragma unroll
    for (int i = 0; i < 8; i++) bia[i] = g_br[ty * 8 + i];
    float* rb = g_r + (size_t)b * CRr * HW;
#pragma unroll
    for (int i = 0; i < 4; i++) {
        float f[2][4];
#pragma unroll
        for (int j = 0; j < 4; j++) {
            float lo, hi;
            UNPACK2(lo, hi, acc2[i][j]);
            f[0][j] = fmaxf(lo + bia[2 * i], 0.f);
            f[1][j] = fmaxf(hi + bia[2 * i + 1], 0.f);
        }
#pragma unroll
        for (int h = 0; h < 2; h++) {
            int m = ty * 8 + 2 * i + h;
            *(float4*)(rb + (size_t)m * HW + n0 + tx * 4) =
                make_float4(f[h][0], f[h][1], f[h][2], f[h][3]);
        }
    }
}

// ---------------- fused span + involution (ker overlaid on rs, 84.5KB) --------
#define TSX  16
#define TSY  8
#define NPX  128
#define XDX  22
#define XDY  14
#define XSTR 20
#define KST  132
#define OFF_RS   0                      // 64k x 128px fp32   = 32768 B
#define OFF_KER  0                      // overlays rs (ker = 25872 B <= 32768)
#define OFF_WS   32768                  // 32 x 52 x 16B      = 26624 B
#define OFF_XS   59392                  // 308 x 20 x 4       = 24640 B
#define OFF_BS   84032                  // 52 x 4
#define SMEM_REQ 84256

extern __shared__ char smraw[];

__global__ __launch_bounds__(256, 2) void fused_kernel(
        const float* __restrict__ x, float* __restrict__ out) {
    int tid  = threadIdx.x;
    int wid  = tid >> 5;
    int lane = tid & 31;
    int bz = blockIdx.z;
    int b = bz >> 4, g = bz & 15;
    int h0 = blockIdx.y * TSY, w0 = blockIdx.x * TSX;
    uint32_t sb = saddr(smraw);

    // ---- cooperative loads: rs + ws + bias --------------------------------------
    {
        const float* rb = g_r + (size_t)b * CRr * HW;
        float* rs = (float*)(smraw + OFF_RS);
#pragma unroll
        for (int it = 0; it < 8; it++) {
            int i = tid + it * 256;          // 2048 float4
            int c = i >> 5, rem = i & 31;
            int y = rem >> 2, x4 = (rem & 3) << 2;
            float4 v = *(const float4*)(rb + (size_t)c * HW + (h0 + y) * Ww + w0 + x4);
            *(float4*)(rs + c * NPX + y * 16 + x4) = v;
        }
    }
    {
        const uint4* src = (const uint4*)g_ws4 + (size_t)g * (32 * NTP);
        uint4* dst = (uint4*)(smraw + OFF_WS);
#pragma unroll
        for (int it = 0; it < 7; it++) {
            int i = tid + it * 256;
            if (i < 32 * NTP) dst[i] = src[i];
        }
    }
    if (tid < NTP)
        ((float*)(smraw + OFF_BS))[tid] = (tid < NT) ? g_bsp[tid * Gg + g] : 0.f;
    __syncthreads();

    // ---- phase 1 compute (warps 0-3) | x halo load (warps 4-7) ------------------
    ull acc2[TPW][2];
    if (wid < 4) {
#pragma unroll
        for (int i = 0; i < TPW; i++) { acc2[i][0] = 0ull; acc2[i][1] = 0ull; }

        uint32_t rs_a = sb + OFF_RS + lane * 16;
        uint32_t ws_a = sb + OFF_WS + wid * TPW * 16;
#pragma unroll 2
        for (int k2 = 0; k2 < 32; k2++) {
            ull b0, b1, c0, c1;
            uint32_t ra = rs_a + k2 * 1024;
            LDSV2(b0, b1, ra);            // k even : px {0,1},{2,3}
            LDSV2(c0, c1, ra + 512);      // k odd
            uint32_t wa = ws_a + k2 * (NTP * 16);
#pragma unroll
            for (int i = 0; i < TPW; i++) {
                ull a0, a1;
                LDSV2(a0, a1, wa + i * 16);
                FMA2(acc2[i][0], a0, b0);
                FMA2(acc2[i][1], a0, b1);
                FMA2(acc2[i][0], a1, c0);
                FMA2(acc2[i][1], a1, c1);
            }
        }
    } else {
        float* xs = (float*)(smraw + OFF_XS);
        const float* xbg = x + (size_t)(b * Cc + g * Dd) * HW;
        int lt = tid - 128;               // 0..127
        for (int idx = lt; idx < Dd * XDY * XDX; idx += 128) {
            int d  = idx / (XDY * XDX);
            int rr = idx - d * (XDY * XDX);
            int yy = rr / XDX;
            int xx = rr - yy * XDX;
            int gy = h0 + yy - Pp;
            int gx = w0 + xx - Pp;
            float v = 0.f;
            if (gy >= 0 && gy < Hh && gx >= 0 && gx < Ww)
                v = xbg[(size_t)d * HW + gy * Ww + gx];
            xs[(yy * XDX + xx) * XSTR + d] = v;
        }
    }
    // all rs reads complete past this barrier -> safe to overlay ker on rs
    __syncthreads();

    // ---- phase 1 epilogue: bias + ker store (into overlaid region) ---------------
    if (wid < 4) {
        float* bs = (float*)(smraw + OFF_BS);
#pragma unroll
        for (int i = 0; i < TPW; i++) {
            int tap = wid * TPW + i;
            if (tap < NT) {
                ull bp;
                float bv = bs[tap];
                PACK2(bp, bv, bv);
                ADD2(acc2[i][0], bp);
                ADD2(acc2[i][1], bp);
                STSV2(sb + OFF_KER + tap * (KST * 4) + lane * 16,
                      acc2[i][0], acc2[i][1]);
            }
        }
    }
    __syncthreads();

    // ---- phase 2: involution (warps 0-3: 4px x 4d sliding window) --------------
    if (wid < 4) {
        float* kerp = (float*)(smraw + OFF_KER);
        int pg = tid >> 2;          // 32 pixel groups of 4
        int dq = tid & 3;
        int p0 = pg * 4;
        int y  = p0 >> 4;           // 0..7
        int x0 = p0 & 15;           // 0,4,8,12
        int d0 = dq * 4;

        ull accb[2][4];             // [d-pair][px]
#pragma unroll
        for (int dp = 0; dp < 2; dp++)
#pragma unroll
            for (int px = 0; px < 4; px++) accb[dp][px] = 0ull;

        uint32_t xs_a = sb + OFF_XS;
#pragma unroll
        for (int ki = 0; ki < 7; ki++) {
            uint32_t xrow = xs_a + (((y + ki) * XDX + x0) * XSTR + d0) * 4;
            ull cur[4][2];
#pragma unroll
            for (int p = 0; p < 3; p++)
                LDSV2(cur[p][0], cur[p][1], xrow + p * (XSTR * 4));
#pragma unroll
            for (int kj = 0; kj < 7; kj++) {
                {
                    int s = (kj + 3) & 3;
                    LDSV2(cur[s][0], cur[s][1], xrow + (kj + 3) * (XSTR * 4));
                }
                float4 kv = *(float4*)(kerp + (ki * 7 + kj) * KST + p0);
                float kvv[4] = {kv.x, kv.y, kv.z, kv.w};
                ull kd[4];
#pragma unroll
                for (int px = 0; px < 4; px++) PACK2(kd[px], kvv[px], kvv[px]);
#pragma unroll
                for (int px = 0; px < 4; px++) {
                    int s = (kj + px) & 3;
                    FMA2(accb[0][px], cur[s][0], kd[px]);
                    FMA2(accb[1][px], cur[s][1], kd[px]);
                }
            }
        }

        float* ob = out + (size_t)(b * Cc + g * Dd + d0) * HW + (h0 + y) * Ww + w0 + x0;
#pragma unroll
        for (int dp = 0; dp < 2; dp++) {
            float lo[4], hi[4];
#pragma unroll
            for (int px = 0; px < 4; px++) UNPACK2(lo[px], hi[px], accb[dp][px]);
            *(float4*)(ob + (size_t)(2 * dp) * HW)     = make_float4(lo[0], lo[1], lo[2], lo[3]);
            *(float4*)(ob + (size_t)(2 * dp + 1) * HW) = make_float4(hi[0], hi[1], hi[2], hi[3]);
        }
    }
}

// ---------------- launcher -----------------------------------------------------
extern "C" void kernel_launch(void* const* d_in, const int* in_sizes, int n_in,
                              void* d_out, int out_size) {
    const float* x        = (const float*)d_in[0];
    const float* v_reduce = (const float*)d_in[1];
    const float* g_reduce = (const float*)d_in[2];
    const float* b_reduce = (const float*)d_in[3];
    const float* bn_gamma = (const float*)d_in[4];
    const float* bn_beta  = (const float*)d_in[5];
    const float* bn_mean  = (const float*)d_in[6];
    const float* bn_var   = (const float*)d_in[7];
    const float* v_span   = (const float*)d_in[8];
    const float* g_span   = (const float*)d_in[9];
    const float* b_span   = (const float*)d_in[10];
    float* out = (float*)d_out;

    static bool attr_set = false;
    if (!attr_set) {
        cudaFuncSetAttribute(fused_kernel,
                             cudaFuncAttributeMaxDynamicSharedMemorySize, SMEM_REQ);
        attr_set = true;
    }

    prep_weights<<<112, 256>>>(v_reduce, g_reduce, b_reduce,
                               bn_gamma, bn_beta, bn_mean, bn_var,
                               v_span, g_span, b_span);

    reduce_gemm<<<dim3(HW / 128, 1, Bb), 256>>>(x);

    fused_kernel<<<dim3(Ww / TSX, Hh / TSY, Bb * Gg), 256, SMEM_REQ>>>(x, out);
}